// round 2
// baseline (speedup 1.0000x reference)
#include <cuda_runtime.h>
#include <math.h>

#define N    8192
#define D    256
#define INV_T (1.0f / 0.7f)

#define BM 64
#define BN 64
#define JCHUNK 1024
#define NBLK_J (N / JCHUNK)   // 8
#define NBLK_I (N / BM)       // 128

// Scratch (static device globals: allocation-free per harness rules)
__device__ float g_PT[D * N];   // normalized projection, TRANSPOSED [k][i]  (8 MB)
__device__ float g_A[N];
__device__ float g_B[N];
__device__ int   g_cls[N];
__device__ int   g_hist[16];
__device__ int   g_is64;        // 1 if y buffer is int64, 0 if int32

// ---------------------------------------------------------------------------
// Kernel D: detect y dtype. If int64 (values in [0,10)), every odd 32-bit
// word is a zero high-word. If int32, ~90% of odd words are nonzero classes.
// P[misdetect] = 0.1^32.
// ---------------------------------------------------------------------------
__global__ void k_detect(const int* __restrict__ y32) {
    int v = y32[2 * threadIdx.x + 1];
    unsigned any = __ballot_sync(0xffffffffu, v != 0);
    if (threadIdx.x == 0) g_is64 = (any == 0) ? 1 : 0;
}

// ---------------------------------------------------------------------------
// Kernel 0: zero accumulators + histogram
// ---------------------------------------------------------------------------
__global__ void k_init() {
    int idx = blockIdx.x * blockDim.x + threadIdx.x;
    if (idx < N) { g_A[idx] = 0.0f; g_B[idx] = 0.0f; }
    if (idx < 16) g_hist[idx] = 0;
}

// ---------------------------------------------------------------------------
// Kernel 1: L2-normalize each row, write transposed; extract class + histogram
// One warp per row (8 rows / 256-thread block).
// ---------------------------------------------------------------------------
__global__ void k_norm(const float* __restrict__ P, const void* __restrict__ yv) {
    int w    = threadIdx.x >> 5;
    int lane = threadIdx.x & 31;
    int row  = blockIdx.x * 8 + w;

    const float4* p4 = (const float4*)(P + (size_t)row * D);
    float4 v0 = p4[lane];        // k = lane*4 .. lane*4+3
    float4 v1 = p4[lane + 32];   // k = 128 + lane*4 ..

    float ss = v0.x*v0.x + v0.y*v0.y + v0.z*v0.z + v0.w*v0.w
             + v1.x*v1.x + v1.y*v1.y + v1.z*v1.z + v1.w*v1.w;
    #pragma unroll
    for (int o = 16; o; o >>= 1) ss += __shfl_xor_sync(0xffffffffu, ss, o);
    float rn = rsqrtf(ss);

    int k0 = lane * 4;
    g_PT[(k0 + 0) * N + row] = v0.x * rn;
    g_PT[(k0 + 1) * N + row] = v0.y * rn;
    g_PT[(k0 + 2) * N + row] = v0.z * rn;
    g_PT[(k0 + 3) * N + row] = v0.w * rn;
    int k1 = 128 + k0;
    g_PT[(k1 + 0) * N + row] = v1.x * rn;
    g_PT[(k1 + 1) * N + row] = v1.y * rn;
    g_PT[(k1 + 2) * N + row] = v1.z * rn;
    g_PT[(k1 + 3) * N + row] = v1.w * rn;

    if (lane == 0) {
        int c;
        if (g_is64) c = (int)((const long long*)yv)[row];
        else        c = ((const int*)yv)[row];
        g_cls[row] = c;
        atomicAdd(&g_hist[c & 15], 1);
    }
}

// ---------------------------------------------------------------------------
// Kernel 2: fused GEMM (P̂ P̂ᵀ tile) + exp epilogue, accumulating A/B per row.
// Grid: (NBLK_I, NBLK_J). Block: 256 threads (16x16), 4x4 outputs each.
// SMEM: sA [256][64] resident, sB [256][64] per j-tile (single-buffered).
// ---------------------------------------------------------------------------
#define SMEM_FLOATS (D*BM + D*BN + BM + BM)
#define SMEM_INTS   (BM + JCHUNK)
#define SMEM_BYTES  ((SMEM_FLOATS + SMEM_INTS) * 4)

__global__ void __launch_bounds__(256, 1) k_main() {
    extern __shared__ float smem[];
    float* sA   = smem;               // [256][64]  k-major
    float* sB   = sA + D * BM;        // [256][64]  k-major
    float* sAcc = sB + D * BN;        // [64]
    float* sBcc = sAcc + BM;          // [64]
    int*   clsI = (int*)(sBcc + BM);  // [64]
    int*   clsJ = clsI + BM;          // [1024]

    const int tid = threadIdx.x;
    const int tx = tid & 15;          // j sub-tile
    const int ty = tid >> 4;          // i sub-tile
    const int iBase  = blockIdx.x * BM;
    const int jBase0 = blockIdx.y * JCHUNK;

    // Load resident sA [k][i] (conflict-free float4 both sides)
    {
        int i4 = (tid & 15) * 4;
        int k0 = tid >> 4;
        #pragma unroll
        for (int kk = k0; kk < D; kk += 16) {
            float4 v = *(const float4*)&g_PT[kk * N + iBase + i4];
            *(float4*)&sA[kk * BM + i4] = v;
        }
    }
    if (tid < BM) {
        clsI[tid] = g_cls[iBase + tid];
        sAcc[tid] = 0.0f;
        sBcc[tid] = 0.0f;
    }
    for (int t = tid; t < JCHUNK; t += 256) clsJ[t] = g_cls[jBase0 + t];

    float aAcc[4] = {0.f, 0.f, 0.f, 0.f};
    float bAcc[4] = {0.f, 0.f, 0.f, 0.f};

    for (int jt = 0; jt < JCHUNK / BN; ++jt) {
        const int jBase = jBase0 + jt * BN;
        __syncthreads();   // previous tile's compute done before overwriting sB
        {
            int j4 = (tid & 15) * 4;
            int k0 = tid >> 4;
            #pragma unroll
            for (int kk = k0; kk < D; kk += 16) {
                float4 v = *(const float4*)&g_PT[kk * N + jBase + j4];
                *(float4*)&sB[kk * BN + j4] = v;
            }
        }
        __syncthreads();

        float acc[4][4];
        #pragma unroll
        for (int a = 0; a < 4; a++)
            #pragma unroll
            for (int b = 0; b < 4; b++) acc[a][b] = 0.f;

        #pragma unroll 4
        for (int k = 0; k < D; ++k) {
            float4 ra = *(const float4*)&sA[k * BM + ty * 4];
            float4 rb = *(const float4*)&sB[k * BN + tx * 4];
            float av[4] = {ra.x, ra.y, ra.z, ra.w};
            float bv[4] = {rb.x, rb.y, rb.z, rb.w};
            #pragma unroll
            for (int a = 0; a < 4; a++)
                #pragma unroll
                for (int b = 0; b < 4; b++)
                    acc[a][b] += av[a] * bv[b];
        }

        // Epilogue: class-masked exp sums
        #pragma unroll
        for (int a = 0; a < 4; a++) {
            const int ci = clsI[ty * 4 + a];
            const int gi = iBase + ty * 4 + a;
            #pragma unroll
            for (int b = 0; b < 4; b++) {
                const int jj = jt * BN + tx * 4 + b;
                const int cj = clsJ[jj];
                const int gj = jBase0 + jj;
                const float s = acc[a][b] * INV_T;
                if (ci == cj) {
                    if (gi != gj) bAcc[a] += __expf(-s);
                } else {
                    aAcc[a] += __expf(s);
                }
            }
        }
    }

    __syncthreads();
    #pragma unroll
    for (int a = 0; a < 4; a++) {
        atomicAdd(&sAcc[ty * 4 + a], aAcc[a]);
        atomicAdd(&sBcc[ty * 4 + a], bAcc[a]);
    }
    __syncthreads();
    if (tid < BM) {
        atomicAdd(&g_A[iBase + tid], sAcc[tid]);
        atomicAdd(&g_B[iBase + tid], sBcc[tid]);
    }
}

// ---------------------------------------------------------------------------
// Kernel 3: per-row loss with exact empty-set semantics, mean-reduce.
// ---------------------------------------------------------------------------
__global__ void k_loss(float* __restrict__ out) {
    __shared__ float red[256];
    const int tid = threadIdx.x;
    const float MF = __expf(0.5f * INV_T);   // exp(margin / T)
    float sum = 0.0f;
    for (int r = tid; r < N; r += 256) {
        int   c    = g_cls[r] & 15;
        int   cnt  = g_hist[c];
        float Av   = (N - cnt > 0) ? g_A[r] : 1.0f;
        float Bv   = (cnt - 1 > 0) ? g_B[r] : 1.0f;
        sum += log1pf(MF * Av * Bv);
    }
    red[tid] = sum;
    __syncthreads();
    #pragma unroll
    for (int s = 128; s; s >>= 1) {
        if (tid < s) red[tid] += red[tid + s];
        __syncthreads();
    }
    if (tid == 0) out[0] = red[0] / (float)N;
}

// ---------------------------------------------------------------------------
extern "C" void kernel_launch(void* const* d_in, const int* in_sizes, int n_in,
                              void* d_out, int out_size) {
    const float* P = (const float*)d_in[0];
    const void*  y = d_in[1];
    float*     out = (float*)d_out;

    cudaFuncSetAttribute(k_main, cudaFuncAttributeMaxDynamicSharedMemorySize,
                         SMEM_BYTES);

    k_detect<<<1, 32>>>((const int*)y);
    k_init<<<(N + 255) / 256, 256>>>();
    k_norm<<<N / 8, 256>>>(P, y);
    dim3 grid(NBLK_I, NBLK_J);
    k_main<<<grid, 256, SMEM_BYTES>>>();
    k_loss<<<1, 256>>>(out);
}

// round 4
// speedup vs baseline: 4.9680x; 4.9680x over previous
#include <cuda_runtime.h>
#include <cuda_bf16.h>
#include <math.h>
#include <stdint.h>

#define N    8192
#define D    256
#define INV_T (1.0f / 0.7f)

#define TM 128
#define TN 128
#define KC 64               // K chunk (bf16 elems)
#define NCHUNK (D / KC)     // 4
#define GI (N / TM)         // 64
#define GJ (N / TN)         // 64

// ---------------- device scratch ----------------
__device__ __nv_bfloat16 g_Pb[N * D];   // normalized rows, bf16, row-major
__device__ float g_A[N];
__device__ float g_B[N];
__device__ int   g_cls[N];
__device__ int   g_hist[16];
__device__ int   g_is64;

// ---------------- helpers (baseline PTX only) ----------------
__device__ __forceinline__ uint32_t smem_u32(const void* p) {
    uint32_t a;
    asm("{ .reg .u64 t; cvta.to.shared.u64 t, %1; cvt.u32.u64 %0, t; }"
        : "=r"(a) : "l"(p));
    return a;
}
#define SW128(off) ((off) ^ (((off) >> 3) & 0x70))

__device__ __forceinline__ void cp16(uint32_t dst, const void* src) {
    asm volatile("cp.async.cg.shared.global [%0], [%1], 16;"
                 :: "r"(dst), "l"(src));
}
__device__ __forceinline__ void cp_commit() {
    asm volatile("cp.async.commit_group;" ::: "memory");
}
__device__ __forceinline__ void ldsm4(uint32_t& r0, uint32_t& r1,
                                      uint32_t& r2, uint32_t& r3, uint32_t addr) {
    asm volatile("ldmatrix.sync.aligned.m8n8.x4.shared.b16 {%0,%1,%2,%3}, [%4];"
                 : "=r"(r0), "=r"(r1), "=r"(r2), "=r"(r3) : "r"(addr));
}
__device__ __forceinline__ void mma16816(float* d, const uint32_t* a,
                                         const uint32_t* b) {
    asm volatile("mma.sync.aligned.m16n8k16.row.col.f32.bf16.bf16.f32 "
                 "{%0,%1,%2,%3}, {%4,%5,%6,%7}, {%8,%9}, {%0,%1,%2,%3};"
                 : "+f"(d[0]), "+f"(d[1]), "+f"(d[2]), "+f"(d[3])
                 : "r"(a[0]), "r"(a[1]), "r"(a[2]), "r"(a[3]),
                   "r"(b[0]), "r"(b[1]));
}

// ---------------- SMEM layout ----------------
// bufA[2]: 0 / 16384 ; bufB[2]: 32768 / 49152  (each chunk: 128 rows x 128 B, SW128)
#define AOFF(b) ((b) * 16384)
#define BOFF(b) (32768 + (b) * 16384)
#define CLSI_OFF 65536
#define CLSJ_OFF 66048
#define SACC_OFF 66560
#define SBCC_OFF 67072
#define SMEM_BYTES 67584

// ---------------------------------------------------------------------------
__global__ void k_detect(const int* __restrict__ y32) {
    int v = y32[2 * threadIdx.x + 1];
    unsigned any = __ballot_sync(0xffffffffu, v != 0);
    if (threadIdx.x == 0) g_is64 = (any == 0) ? 1 : 0;
}

__global__ void k_init() {
    int idx = blockIdx.x * blockDim.x + threadIdx.x;
    if (idx < N) { g_A[idx] = 0.0f; g_B[idx] = 0.0f; }
    if (idx < 16) g_hist[idx] = 0;
}

// normalize rows -> bf16 row-major; class + histogram. One warp per row.
__global__ void k_norm(const float* __restrict__ P, const void* __restrict__ yv) {
    int w    = threadIdx.x >> 5;
    int lane = threadIdx.x & 31;
    int row  = blockIdx.x * 8 + w;

    const float4* p4 = (const float4*)(P + (size_t)row * D);
    float4 v0 = p4[lane];
    float4 v1 = p4[lane + 32];

    float ss = v0.x*v0.x + v0.y*v0.y + v0.z*v0.z + v0.w*v0.w
             + v1.x*v1.x + v1.y*v1.y + v1.z*v1.z + v1.w*v1.w;
    #pragma unroll
    for (int o = 16; o; o >>= 1) ss += __shfl_xor_sync(0xffffffffu, ss, o);
    float rn = rsqrtf(ss);

    __nv_bfloat162 a0 = __floats2bfloat162_rn(v0.x * rn, v0.y * rn);
    __nv_bfloat162 a1 = __floats2bfloat162_rn(v0.z * rn, v0.w * rn);
    __nv_bfloat162 b0 = __floats2bfloat162_rn(v1.x * rn, v1.y * rn);
    __nv_bfloat162 b1 = __floats2bfloat162_rn(v1.z * rn, v1.w * rn);

    *(uint2*)(g_Pb + (size_t)row * D + lane * 4) =
        make_uint2(*(uint32_t*)&a0, *(uint32_t*)&a1);
    *(uint2*)(g_Pb + (size_t)row * D + 128 + lane * 4) =
        make_uint2(*(uint32_t*)&b0, *(uint32_t*)&b1);

    if (lane == 0) {
        int c;
        if (g_is64) c = (int)((const long long*)yv)[row];
        else        c = ((const int*)yv)[row];
        g_cls[row] = c;
        atomicAdd(&g_hist[c & 15], 1);
    }
}

// ---------------------------------------------------------------------------
// main: 128x128 sim tile per CTA via mma.sync bf16, cp.async double buffer,
// fused class-masked exp epilogue.
// ---------------------------------------------------------------------------
__global__ void __launch_bounds__(256) k_main() {
    extern __shared__ __align__(128) unsigned char smem[];
    const uint32_t sbase = smem_u32(smem);
    const int tid  = threadIdx.x;
    const int wid  = tid >> 5;
    const int lane = tid & 31;

    const int iBase = blockIdx.x * TM;
    const int jBase = blockIdx.y * TN;

    int*   clsI = (int*)(smem + CLSI_OFF);
    int*   clsJ = (int*)(smem + CLSJ_OFF);
    float* sAcc = (float*)(smem + SACC_OFF);
    float* sBcc = (float*)(smem + SBCC_OFF);

    if (tid < 128) { clsI[tid] = g_cls[iBase + tid]; sAcc[tid] = 0.0f; sBcc[tid] = 0.0f; }
    else           { clsJ[tid - 128] = g_cls[jBase + tid - 128]; }

    // ---- async load of chunk ck into buffer b ----
    auto load_chunk = [&](int ck, int b) {
        #pragma unroll
        for (int q = 0; q < 4; q++) {
            int s  = tid + q * 256;      // 0..1023
            int r  = s >> 3;
            int sg = s & 7;
            uint32_t soff = SW128((uint32_t)(r * 128 + sg * 16));
            cp16(sbase + AOFF(b) + soff,
                 g_Pb + (size_t)(iBase + r) * D + ck * KC + sg * 8);
            cp16(sbase + BOFF(b) + soff,
                 g_Pb + (size_t)(jBase + r) * D + ck * KC + sg * 8);
        }
    };

    load_chunk(0, 0); cp_commit();
    load_chunk(1, 1); cp_commit();

    const int warp_m = wid >> 2;       // 0..1
    const int warp_n = wid & 3;        // 0..3
    const int m0 = warp_m * 64;
    const int n0 = warp_n * 32;
    const int lrow  = lane & 15;
    const int lkoff = (lane >> 4) * 16;   // byte offset of k-half

    float acc[4][4][4];
    #pragma unroll
    for (int mf = 0; mf < 4; mf++)
        #pragma unroll
        for (int nf = 0; nf < 4; nf++)
            #pragma unroll
            for (int e = 0; e < 4; e++) acc[mf][nf][e] = 0.0f;

    #pragma unroll
    for (int ck = 0; ck < NCHUNK; ck++) {
        if (ck < NCHUNK - 1) asm volatile("cp.async.wait_group 1;" ::: "memory");
        else                 asm volatile("cp.async.wait_group 0;" ::: "memory");
        __syncthreads();

        const uint32_t aB = sbase + AOFF(ck & 1);
        const uint32_t bB = sbase + BOFF(ck & 1);

        #pragma unroll
        for (int ks = 0; ks < 4; ks++) {
            uint32_t afr[4][4];
            #pragma unroll
            for (int mf = 0; mf < 4; mf++) {
                uint32_t off = (uint32_t)((m0 + mf * 16 + lrow) * 128 + lkoff + ks * 32);
                ldsm4(afr[mf][0], afr[mf][1], afr[mf][2], afr[mf][3], aB + SW128(off));
            }
            uint32_t bfr[4][2];
            #pragma unroll
            for (int nf2 = 0; nf2 < 2; nf2++) {
                uint32_t r0, r1, r2, r3;
                uint32_t off = (uint32_t)((n0 + nf2 * 16 + lrow) * 128 + lkoff + ks * 32);
                ldsm4(r0, r1, r2, r3, bB + SW128(off));
                bfr[nf2 * 2 + 0][0] = r0; bfr[nf2 * 2 + 0][1] = r2;
                bfr[nf2 * 2 + 1][0] = r1; bfr[nf2 * 2 + 1][1] = r3;
            }
            #pragma unroll
            for (int mf = 0; mf < 4; mf++)
                #pragma unroll
                for (int nf = 0; nf < 4; nf++)
                    mma16816(acc[mf][nf], afr[mf], bfr[nf]);
        }
        __syncthreads();
        if (ck < NCHUNK - 2) { load_chunk(ck + 2, ck & 1); cp_commit(); }
    }

    // ---- epilogue: masked exp sums ----
    const int gl   = lane >> 2;   // 0..7
    const int quad = lane & 3;    // 0..3
    #pragma unroll
    for (int rr = 0; rr < 2; rr++) {
        #pragma unroll
        for (int mf = 0; mf < 4; mf++) {
            const int rl = m0 + mf * 16 + gl + rr * 8;
            const int ci = clsI[rl];
            const int gi = iBase + rl;
            float aA = 0.0f, bBv = 0.0f;
            #pragma unroll
            for (int nf = 0; nf < 4; nf++) {
                #pragma unroll
                for (int e = 0; e < 2; e++) {
                    const int cl = n0 + nf * 8 + quad * 2 + e;
                    const float s = acc[mf][nf][rr * 2 + e] * INV_T;
                    const int cj = clsJ[cl];
                    if (ci == cj) {
                        if (gi != jBase + cl) bBv += __expf(-s);
                    } else {
                        aA += __expf(s);
                    }
                }
            }
            aA  += __shfl_xor_sync(0xffffffffu, aA, 1);
            aA  += __shfl_xor_sync(0xffffffffu, aA, 2);
            bBv += __shfl_xor_sync(0xffffffffu, bBv, 1);
            bBv += __shfl_xor_sync(0xffffffffu, bBv, 2);
            if (quad == 0) {
                atomicAdd(&sAcc[rl], aA);
                atomicAdd(&sBcc[rl], bBv);
            }
        }
    }
    __syncthreads();
    if (tid < 128) {
        atomicAdd(&g_A[iBase + tid], sAcc[tid]);
        atomicAdd(&g_B[iBase + tid], sBcc[tid]);
    }
}

// ---------------------------------------------------------------------------
__global__ void k_loss(float* __restrict__ out) {
    __shared__ float red[256];
    const int tid = threadIdx.x;
    const float MF = __expf(0.5f * INV_T);
    float sum = 0.0f;
    for (int r = tid; r < N; r += 256) {
        int   c   = g_cls[r] & 15;
        int   cnt = g_hist[c];
        float Av  = (N - cnt > 0) ? g_A[r] : 1.0f;
        float Bv  = (cnt - 1 > 0) ? g_B[r] : 1.0f;
        sum += log1pf(MF * Av * Bv);
    }
    red[tid] = sum;
    __syncthreads();
    #pragma unroll
    for (int s = 128; s; s >>= 1) {
        if (tid < s) red[tid] += red[tid + s];
        __syncthreads();
    }
    if (tid == 0) out[0] = red[0] / (float)N;
}

// ---------------------------------------------------------------------------
extern "C" void kernel_launch(void* const* d_in, const int* in_sizes, int n_in,
                              void* d_out, int out_size) {
    const float* P = (const float*)d_in[0];
    const void*  y = d_in[1];
    float*     out = (float*)d_out;

    cudaFuncSetAttribute(k_main, cudaFuncAttributeMaxDynamicSharedMemorySize,
                         SMEM_BYTES);

    k_detect<<<1, 32>>>((const int*)y);
    k_init<<<(N + 255) / 256, 256>>>();
    k_norm<<<N / 8, 256>>>(P, y);
    dim3 grid(GI, GJ);
    k_main<<<grid, 256, SMEM_BYTES>>>();
    k_loss<<<1, 256>>>(out);
}

// round 5
// speedup vs baseline: 8.8056x; 1.7725x over previous
#include <cuda_runtime.h>
#include <cuda_bf16.h>
#include <math.h>
#include <stdint.h>

#define N    8192
#define D    256
#define INV_T (1.0f / 0.7f)

#define TM 128
#define TN 128
#define KC 64               // K chunk (bf16 elems)
#define NCHUNK (D / KC)     // 4
#define GI (N / TM)         // 64
#define NTILES (GI * (GI + 1) / 2)   // 2080 upper-triangle tiles

// ---------------- device scratch ----------------
__device__ __nv_bfloat16 g_Pb[N * D];   // normalized rows, bf16, row-major
__device__ float g_A[N];
__device__ float g_B[N];
__device__ int   g_cls[N];
__device__ int   g_hist[16];
__device__ int   g_is64;

// ---------------- helpers (baseline PTX only) ----------------
__device__ __forceinline__ uint32_t smem_u32(const void* p) {
    uint32_t a;
    asm("{ .reg .u64 t; cvta.to.shared.u64 t, %1; cvt.u32.u64 %0, t; }"
        : "=r"(a) : "l"(p));
    return a;
}
#define SW128(off) ((off) ^ (((off) >> 3) & 0x70))

__device__ __forceinline__ void cp16(uint32_t dst, const void* src) {
    asm volatile("cp.async.cg.shared.global [%0], [%1], 16;"
                 :: "r"(dst), "l"(src));
}
__device__ __forceinline__ void cp_commit() {
    asm volatile("cp.async.commit_group;" ::: "memory");
}
__device__ __forceinline__ void ldsm4(uint32_t& r0, uint32_t& r1,
                                      uint32_t& r2, uint32_t& r3, uint32_t addr) {
    asm volatile("ldmatrix.sync.aligned.m8n8.x4.shared.b16 {%0,%1,%2,%3}, [%4];"
                 : "=r"(r0), "=r"(r1), "=r"(r2), "=r"(r3) : "r"(addr));
}
__device__ __forceinline__ void mma16816(float* d, const uint32_t* a,
                                         const uint32_t* b) {
    asm volatile("mma.sync.aligned.m16n8k16.row.col.f32.bf16.bf16.f32 "
                 "{%0,%1,%2,%3}, {%4,%5,%6,%7}, {%8,%9}, {%0,%1,%2,%3};"
                 : "+f"(d[0]), "+f"(d[1]), "+f"(d[2]), "+f"(d[3])
                 : "r"(a[0]), "r"(a[1]), "r"(a[2]), "r"(a[3]),
                   "r"(b[0]), "r"(b[1]));
}

// ---------------- SMEM layout ----------------
#define AOFF(b) ((b) * 16384)
#define BOFF(b) (32768 + (b) * 16384)
#define CLSI_OFF  65536
#define CLSJ_OFF  66048
#define SACCI_OFF 66560
#define SBCCI_OFF 67072
#define SACCJ_OFF 67584
#define SBCCJ_OFF 68096
#define SMEM_BYTES 68608

// ---------------------------------------------------------------------------
__global__ void k_detect(const int* __restrict__ y32) {
    int v = y32[2 * threadIdx.x + 1];
    unsigned any = __ballot_sync(0xffffffffu, v != 0);
    if (threadIdx.x == 0) g_is64 = (any == 0) ? 1 : 0;
}

__global__ void k_init() {
    int idx = blockIdx.x * blockDim.x + threadIdx.x;
    if (idx < N) { g_A[idx] = 0.0f; g_B[idx] = 0.0f; }
    if (idx < 16) g_hist[idx] = 0;
}

// normalize rows -> bf16 row-major; class + histogram. One warp per row.
__global__ void k_norm(const float* __restrict__ P, const void* __restrict__ yv) {
    int w    = threadIdx.x >> 5;
    int lane = threadIdx.x & 31;
    int row  = blockIdx.x * 8 + w;

    const float4* p4 = (const float4*)(P + (size_t)row * D);
    float4 v0 = p4[lane];
    float4 v1 = p4[lane + 32];

    float ss = v0.x*v0.x + v0.y*v0.y + v0.z*v0.z + v0.w*v0.w
             + v1.x*v1.x + v1.y*v1.y + v1.z*v1.z + v1.w*v1.w;
    #pragma unroll
    for (int o = 16; o; o >>= 1) ss += __shfl_xor_sync(0xffffffffu, ss, o);
    float rn = rsqrtf(ss);

    __nv_bfloat162 a0 = __floats2bfloat162_rn(v0.x * rn, v0.y * rn);
    __nv_bfloat162 a1 = __floats2bfloat162_rn(v0.z * rn, v0.w * rn);
    __nv_bfloat162 b0 = __floats2bfloat162_rn(v1.x * rn, v1.y * rn);
    __nv_bfloat162 b1 = __floats2bfloat162_rn(v1.z * rn, v1.w * rn);

    *(uint2*)(g_Pb + (size_t)row * D + lane * 4) =
        make_uint2(*(uint32_t*)&a0, *(uint32_t*)&a1);
    *(uint2*)(g_Pb + (size_t)row * D + 128 + lane * 4) =
        make_uint2(*(uint32_t*)&b0, *(uint32_t*)&b1);

    if (lane == 0) {
        int c;
        if (g_is64) c = (int)((const long long*)yv)[row];
        else        c = ((const int*)yv)[row];
        g_cls[row] = c;
        atomicAdd(&g_hist[c & 15], 1);
    }
}

// ---------------------------------------------------------------------------
// main: upper-triangle 128x128 tiles; each off-diagonal tile feeds BOTH its
// row block (i-sums) and column block (j-sums) from a single set of exps.
// ---------------------------------------------------------------------------
__global__ void __launch_bounds__(256, 2) k_main() {
    extern __shared__ __align__(128) unsigned char smem[];
    const uint32_t sbase = smem_u32(smem);
    const int tid  = threadIdx.x;
    const int wid  = tid >> 5;
    const int lane = tid & 31;

    // map linear tile id -> (biBlk, bjBlk) with biBlk <= bjBlk
    int biBlk = 0, rem = blockIdx.x;
    #pragma unroll 1
    while (rem >= GI - biBlk) { rem -= GI - biBlk; biBlk++; }
    const int bjBlk = biBlk + rem;
    const bool offdiag = (biBlk != bjBlk);

    const int iBase = biBlk * TM;
    const int jBase = bjBlk * TN;

    int*   clsI  = (int*)(smem + CLSI_OFF);
    int*   clsJ  = (int*)(smem + CLSJ_OFF);
    float* sAccI = (float*)(smem + SACCI_OFF);
    float* sBccI = (float*)(smem + SBCCI_OFF);
    float* sAccJ = (float*)(smem + SACCJ_OFF);
    float* sBccJ = (float*)(smem + SBCCJ_OFF);

    if (tid < 128) {
        clsI[tid] = g_cls[iBase + tid];
        sAccI[tid] = 0.0f; sBccI[tid] = 0.0f;
    } else {
        clsJ[tid - 128] = g_cls[jBase + tid - 128];
        sAccJ[tid - 128] = 0.0f; sBccJ[tid - 128] = 0.0f;
    }

    auto load_chunk = [&](int ck, int b) {
        #pragma unroll
        for (int q = 0; q < 4; q++) {
            int s  = tid + q * 256;
            int r  = s >> 3;
            int sg = s & 7;
            uint32_t soff = SW128((uint32_t)(r * 128 + sg * 16));
            cp16(sbase + AOFF(b) + soff,
                 g_Pb + (size_t)(iBase + r) * D + ck * KC + sg * 8);
            cp16(sbase + BOFF(b) + soff,
                 g_Pb + (size_t)(jBase + r) * D + ck * KC + sg * 8);
        }
    };

    load_chunk(0, 0); cp_commit();
    load_chunk(1, 1); cp_commit();

    const int warp_m = wid >> 2;
    const int warp_n = wid & 3;
    const int m0 = warp_m * 64;
    const int n0 = warp_n * 32;
    const int lrow  = lane & 15;
    const int lkoff = (lane >> 4) * 16;

    float acc[4][4][4];
    #pragma unroll
    for (int mf = 0; mf < 4; mf++)
        #pragma unroll
        for (int nf = 0; nf < 4; nf++)
            #pragma unroll
            for (int e = 0; e < 4; e++) acc[mf][nf][e] = 0.0f;

    #pragma unroll
    for (int ck = 0; ck < NCHUNK; ck++) {
        if (ck < NCHUNK - 1) asm volatile("cp.async.wait_group 1;" ::: "memory");
        else                 asm volatile("cp.async.wait_group 0;" ::: "memory");
        __syncthreads();

        const uint32_t aB = sbase + AOFF(ck & 1);
        const uint32_t bB = sbase + BOFF(ck & 1);

        #pragma unroll
        for (int ks = 0; ks < 4; ks++) {
            uint32_t afr[4][4];
            #pragma unroll
            for (int mf = 0; mf < 4; mf++) {
                uint32_t off = (uint32_t)((m0 + mf * 16 + lrow) * 128 + lkoff + ks * 32);
                ldsm4(afr[mf][0], afr[mf][1], afr[mf][2], afr[mf][3], aB + SW128(off));
            }
            uint32_t bfr[4][2];
            #pragma unroll
            for (int nf2 = 0; nf2 < 2; nf2++) {
                uint32_t r0, r1, r2, r3;
                uint32_t off = (uint32_t)((n0 + nf2 * 16 + lrow) * 128 + lkoff + ks * 32);
                ldsm4(r0, r1, r2, r3, bB + SW128(off));
                bfr[nf2 * 2 + 0][0] = r0; bfr[nf2 * 2 + 0][1] = r2;
                bfr[nf2 * 2 + 1][0] = r1; bfr[nf2 * 2 + 1][1] = r3;
            }
            #pragma unroll
            for (int mf = 0; mf < 4; mf++)
                #pragma unroll
                for (int nf = 0; nf < 4; nf++)
                    mma16816(acc[mf][nf], afr[mf], bfr[nf]);
        }
        __syncthreads();
        if (ck < NCHUNK - 2) { load_chunk(ck + 2, ck & 1); cp_commit(); }
    }

    // ---- epilogue: masked exp; row sums + (off-diag) column sums ----
    const int gl   = lane >> 2;   // 0..7
    const int quad = lane & 3;    // 0..3

    float aCol[4][2], bCol[4][2];
    #pragma unroll
    for (int nf = 0; nf < 4; nf++)
        #pragma unroll
        for (int e = 0; e < 2; e++) { aCol[nf][e] = 0.0f; bCol[nf][e] = 0.0f; }

    #pragma unroll
    for (int rr = 0; rr < 2; rr++) {
        #pragma unroll
        for (int mf = 0; mf < 4; mf++) {
            const int rl = m0 + mf * 16 + gl + rr * 8;
            const int ci = clsI[rl];
            const int gi = iBase + rl;
            float aRow = 0.0f, bRow = 0.0f;
            #pragma unroll
            for (int nf = 0; nf < 4; nf++) {
                #pragma unroll
                for (int e = 0; e < 2; e++) {
                    const int cl = n0 + nf * 8 + quad * 2 + e;
                    const float s = acc[mf][nf][rr * 2 + e] * INV_T;
                    const int cj = clsJ[cl];
                    if (ci == cj) {
                        if (gi != jBase + cl) {
                            float v = __expf(-s);
                            bRow += v; bCol[nf][e] += v;
                        }
                    } else {
                        float v = __expf(s);
                        aRow += v; aCol[nf][e] += v;
                    }
                }
            }
            aRow += __shfl_xor_sync(0xffffffffu, aRow, 1);
            aRow += __shfl_xor_sync(0xffffffffu, aRow, 2);
            bRow += __shfl_xor_sync(0xffffffffu, bRow, 1);
            bRow += __shfl_xor_sync(0xffffffffu, bRow, 2);
            if (quad == 0) {
                atomicAdd(&sAccI[rl], aRow);
                atomicAdd(&sBccI[rl], bRow);
            }
        }
    }

    if (offdiag) {
        // reduce column partials across the 8 gl-lane groups (lane^4,8,16)
        #pragma unroll
        for (int nf = 0; nf < 4; nf++) {
            #pragma unroll
            for (int e = 0; e < 2; e++) {
                float a = aCol[nf][e], b = bCol[nf][e];
                #pragma unroll
                for (int o = 4; o <= 16; o <<= 1) {
                    a += __shfl_xor_sync(0xffffffffu, a, o);
                    b += __shfl_xor_sync(0xffffffffu, b, o);
                }
                if (lane < 4) {
                    const int cl = n0 + nf * 8 + quad * 2 + e;
                    atomicAdd(&sAccJ[cl], a);
                    atomicAdd(&sBccJ[cl], b);
                }
            }
        }
    }

    __syncthreads();
    if (tid < 128) {
        atomicAdd(&g_A[iBase + tid], sAccI[tid]);
        atomicAdd(&g_B[iBase + tid], sBccI[tid]);
        if (offdiag) {
            atomicAdd(&g_A[jBase + tid], sAccJ[tid]);
            atomicAdd(&g_B[jBase + tid], sBccJ[tid]);
        }
    }
}

// ---------------------------------------------------------------------------
__global__ void k_loss(float* __restrict__ out) {
    __shared__ float red[256];
    const int tid = threadIdx.x;
    const float MF = __expf(0.5f * INV_T);
    float sum = 0.0f;
    for (int r = tid; r < N; r += 256) {
        int   c   = g_cls[r] & 15;
        int   cnt = g_hist[c];
        float Av  = (N - cnt > 0) ? g_A[r] : 1.0f;
        float Bv  = (cnt - 1 > 0) ? g_B[r] : 1.0f;
        sum += log1pf(MF * Av * Bv);
    }
    red[tid] = sum;
    __syncthreads();
    #pragma unroll
    for (int s = 128; s; s >>= 1) {
        if (tid < s) red[tid] += red[tid + s];
        __syncthreads();
    }
    if (tid == 0) out[0] = red[0] / (float)N;
}

// ---------------------------------------------------------------------------
extern "C" void kernel_launch(void* const* d_in, const int* in_sizes, int n_in,
                              void* d_out, int out_size) {
    const float* P = (const float*)d_in[0];
    const void*  y = d_in[1];
    float*     out = (float*)d_out;

    cudaFuncSetAttribute(k_main, cudaFuncAttributeMaxDynamicSharedMemorySize,
                         SMEM_BYTES);

    k_detect<<<1, 32>>>((const int*)y);
    k_init<<<(N + 255) / 256, 256>>>();
    k_norm<<<N / 8, 256>>>(P, y);
    k_main<<<NTILES, 256, SMEM_BYTES>>>();
    k_loss<<<1, 256>>>(out);
}

// round 6
// speedup vs baseline: 9.6777x; 1.0990x over previous
#include <cuda_runtime.h>
#include <cuda_bf16.h>
#include <math.h>
#include <stdint.h>

#define N    8192
#define D    256
#define INV_T (1.0f / 0.7f)
#define EX2SC (1.44269504088896f * INV_T)   // log2(e)/T

#define TM 128
#define TN 128
#define GI (N / TM)                  // 64
#define NTILES (GI * (GI + 1) / 2)   // 2080

// ---------------- device scratch ----------------
__device__ __nv_bfloat16 g_Pb[N * D];
__device__ float g_A[N];
__device__ float g_B[N];
__device__ float g_selfsim[N];
__device__ int   g_cls[N];

// ---------------- helpers ----------------
__device__ __forceinline__ uint32_t smem_u32(const void* p) {
    uint32_t a;
    asm("{ .reg .u64 t; cvta.to.shared.u64 t, %1; cvt.u32.u64 %0, t; }"
        : "=r"(a) : "l"(p));
    return a;
}
#define SW128(off) ((off) ^ (((off) >> 3) & 0x70))

__device__ __forceinline__ void cp16(uint32_t dst, const void* src) {
    asm volatile("cp.async.cg.shared.global [%0], [%1], 16;" :: "r"(dst), "l"(src));
}
__device__ __forceinline__ void cp_commit() {
    asm volatile("cp.async.commit_group;" ::: "memory");
}
__device__ __forceinline__ void ldsm4(uint32_t& r0, uint32_t& r1,
                                      uint32_t& r2, uint32_t& r3, uint32_t addr) {
    asm volatile("ldmatrix.sync.aligned.m8n8.x4.shared.b16 {%0,%1,%2,%3}, [%4];"
                 : "=r"(r0), "=r"(r1), "=r"(r2), "=r"(r3) : "r"(addr));
}
__device__ __forceinline__ void mma16816(float* d, const uint32_t* a,
                                         const uint32_t* b) {
    asm volatile("mma.sync.aligned.m16n8k16.row.col.f32.bf16.bf16.f32 "
                 "{%0,%1,%2,%3}, {%4,%5,%6,%7}, {%8,%9}, {%0,%1,%2,%3};"
                 : "+f"(d[0]), "+f"(d[1]), "+f"(d[2]), "+f"(d[3])
                 : "r"(a[0]), "r"(a[1]), "r"(a[2]), "r"(a[3]),
                   "r"(b[0]), "r"(b[1]));
}
__device__ __forceinline__ float ex2(float x) {
    float r;
    asm("ex2.approx.f32 %0, %1;" : "=f"(r) : "f"(x));
    return r;
}

// ---------------- SMEM layout: all 4 chunks resident ----------------
#define ACH(c) ((c) * 16384)             // A chunk c: 128 rows x 128 B (SW128)
#define BCH(c) (65536 + (c) * 16384)
#define CLSI_OFF  131072
#define CLSJ_OFF  131584
#define SACCI_OFF 132096
#define SBCCI_OFF 132608
#define SACCJ_OFF 133120
#define SBCCJ_OFF 133632
#define SMEM_BYTES 134144

// ---------------------------------------------------------------------------
// k_norm: dtype detect + zero A/B + normalize->bf16 + selfsim + class
// ---------------------------------------------------------------------------
__global__ void k_norm(const float* __restrict__ P, const void* __restrict__ yv) {
    __shared__ int s_is64;
    const int tid  = threadIdx.x;
    const int w    = tid >> 5;
    const int lane = tid & 31;
    const int row  = blockIdx.x * 8 + w;

    if (w == 0) {   // detect: int64 y<10 => all odd words zero
        int v = ((const int*)yv)[2 * lane + 1];
        unsigned any = __ballot_sync(0xffffffffu, v != 0);
        if (lane == 0) s_is64 = (any == 0) ? 1 : 0;
    }
    if (blockIdx.x < 32) {              // zero accumulators
        int idx = blockIdx.x * 256 + tid;
        g_A[idx] = 0.0f; g_B[idx] = 0.0f;
    }
    __syncthreads();
    const int is64 = s_is64;

    const float4* p4 = (const float4*)(P + (size_t)row * D);
    float4 v0 = p4[lane];
    float4 v1 = p4[lane + 32];

    float ss = v0.x*v0.x + v0.y*v0.y + v0.z*v0.z + v0.w*v0.w
             + v1.x*v1.x + v1.y*v1.y + v1.z*v1.z + v1.w*v1.w;
    #pragma unroll
    for (int o = 16; o; o >>= 1) ss += __shfl_xor_sync(0xffffffffu, ss, o);
    float rn = rsqrtf(ss);

    __nv_bfloat16 h[8];
    h[0] = __float2bfloat16(v0.x * rn); h[1] = __float2bfloat16(v0.y * rn);
    h[2] = __float2bfloat16(v0.z * rn); h[3] = __float2bfloat16(v0.w * rn);
    h[4] = __float2bfloat16(v1.x * rn); h[5] = __float2bfloat16(v1.y * rn);
    h[6] = __float2bfloat16(v1.z * rn); h[7] = __float2bfloat16(v1.w * rn);

    // self-sim of the bf16-rounded row (what the MMA will compute on diag)
    float sb = 0.0f;
    #pragma unroll
    for (int q = 0; q < 8; q++) { float f = __bfloat162float(h[q]); sb += f * f; }
    #pragma unroll
    for (int o = 16; o; o >>= 1) sb += __shfl_xor_sync(0xffffffffu, sb, o);

    *(uint2*)(g_Pb + (size_t)row * D + lane * 4)       = *(uint2*)&h[0];
    *(uint2*)(g_Pb + (size_t)row * D + 128 + lane * 4) = *(uint2*)&h[4];

    if (lane == 0) {
        int c = is64 ? (int)((const long long*)yv)[row] : ((const int*)yv)[row];
        g_cls[row]     = c;
        g_selfsim[row] = sb;
    }
}

// ---------------------------------------------------------------------------
// fragment load for one ks step (B first so A's scoreboard drains last)
// ---------------------------------------------------------------------------
__device__ __forceinline__ void load_frags(uint32_t aB, uint32_t bB, int ks,
                                           int m0, int n0, int lrow, int lkoff,
                                           uint32_t afr[4][4], uint32_t bfr[4][2]) {
    #pragma unroll
    for (int nf2 = 0; nf2 < 2; nf2++) {
        uint32_t r0, r1, r2, r3;
        uint32_t off = (uint32_t)((n0 + nf2 * 16 + lrow) * 128 + lkoff + ks * 32);
        ldsm4(r0, r1, r2, r3, bB + SW128(off));
        bfr[nf2 * 2 + 0][0] = r0; bfr[nf2 * 2 + 0][1] = r2;
        bfr[nf2 * 2 + 1][0] = r1; bfr[nf2 * 2 + 1][1] = r3;
    }
    #pragma unroll
    for (int mf = 0; mf < 4; mf++) {
        uint32_t off = (uint32_t)((m0 + mf * 16 + lrow) * 128 + lkoff + ks * 32);
        ldsm4(afr[mf][0], afr[mf][1], afr[mf][2], afr[mf][3], aB + SW128(off));
    }
}

template<int CK>
__device__ __forceinline__ void do_chunk(uint32_t sbase, int m0, int n0,
                                         int lrow, int lkoff,
                                         uint32_t afr[2][4][4], uint32_t bfr[2][4][2],
                                         float acc[4][4][4]) {
    asm volatile("cp.async.wait_group %0;" :: "n"(3 - CK) : "memory");
    __syncthreads();
    const uint32_t aB = sbase + ACH(CK);
    const uint32_t bB = sbase + BCH(CK);
    load_frags(aB, bB, 0, m0, n0, lrow, lkoff, afr[0], bfr[0]);
    #pragma unroll
    for (int ks = 0; ks < 4; ks++) {
        const int cur = ks & 1;
        if (ks < 3)
            load_frags(aB, bB, ks + 1, m0, n0, lrow, lkoff, afr[cur ^ 1], bfr[cur ^ 1]);
        #pragma unroll
        for (int mf = 0; mf < 4; mf++)
            #pragma unroll
            for (int nf = 0; nf < 4; nf++)
                mma16816(acc[mf][nf], afr[cur][mf], bfr[cur][nf]);
    }
}

// ---------------------------------------------------------------------------
// k_main: upper-triangle tiles, all-resident SMEM, reg-pipelined fragments
// ---------------------------------------------------------------------------
__global__ void __launch_bounds__(256, 1) k_main() {
    extern __shared__ __align__(128) unsigned char smem[];
    const uint32_t sbase = smem_u32(smem);
    const int tid  = threadIdx.x;
    const int wid  = tid >> 5;
    const int lane = tid & 31;

    int biBlk = 0, rem = blockIdx.x;
    #pragma unroll 1
    while (rem >= GI - biBlk) { rem -= GI - biBlk; biBlk++; }
    const int bjBlk = biBlk + rem;
    const bool offdiag = (biBlk != bjBlk);

    const int iBase = biBlk * TM;
    const int jBase = bjBlk * TN;

    int*   clsI  = (int*)(smem + CLSI_OFF);
    int*   clsJ  = (int*)(smem + CLSJ_OFF);
    float* sAccI = (float*)(smem + SACCI_OFF);
    float* sBccI = (float*)(smem + SBCCI_OFF);
    float* sAccJ = (float*)(smem + SACCJ_OFF);
    float* sBccJ = (float*)(smem + SBCCJ_OFF);

    // issue all 4 chunks as 4 cp.async groups
    #pragma unroll
    for (int ck = 0; ck < 4; ck++) {
        #pragma unroll
        for (int q = 0; q < 4; q++) {
            int s  = tid + q * 256;
            int r  = s >> 3;
            int sg = s & 7;
            uint32_t soff = SW128((uint32_t)(r * 128 + sg * 16));
            cp16(sbase + ACH(ck) + soff,
                 g_Pb + (size_t)(iBase + r) * D + ck * 64 + sg * 8);
            cp16(sbase + BCH(ck) + soff,
                 g_Pb + (size_t)(jBase + r) * D + ck * 64 + sg * 8);
        }
        cp_commit();
    }

    if (tid < 128) {
        clsI[tid] = g_cls[iBase + tid];
        sAccI[tid] = 0.0f; sBccI[tid] = 0.0f;
    } else {
        clsJ[tid - 128] = g_cls[jBase + tid - 128];
        sAccJ[tid - 128] = 0.0f; sBccJ[tid - 128] = 0.0f;
    }

    const int m0 = (wid >> 2) * 64;
    const int n0 = (wid & 3) * 32;
    const int lrow  = lane & 15;
    const int lkoff = (lane >> 4) * 16;

    float acc[4][4][4];
    #pragma unroll
    for (int mf = 0; mf < 4; mf++)
        #pragma unroll
        for (int nf = 0; nf < 4; nf++)
            #pragma unroll
            for (int e = 0; e < 4; e++) acc[mf][nf][e] = 0.0f;

    uint32_t afr[2][4][4], bfr[2][4][2];
    do_chunk<0>(sbase, m0, n0, lrow, lkoff, afr, bfr, acc);
    do_chunk<1>(sbase, m0, n0, lrow, lkoff, afr, bfr, acc);
    do_chunk<2>(sbase, m0, n0, lrow, lkoff, afr, bfr, acc);
    do_chunk<3>(sbase, m0, n0, lrow, lkoff, afr, bfr, acc);

    // ---- epilogue (no diagonal special-case; self term removed in k_loss) ----
    const int gl   = lane >> 2;
    const int quad = lane & 3;

    int cjr[8];
    #pragma unroll
    for (int q = 0; q < 8; q++) cjr[q] = clsJ[n0 + (q >> 1) * 8 + quad * 2 + (q & 1)];

    float aCol[8], bCol[8];
    #pragma unroll
    for (int q = 0; q < 8; q++) { aCol[q] = 0.0f; bCol[q] = 0.0f; }

    #pragma unroll
    for (int rr = 0; rr < 2; rr++) {
        #pragma unroll
        for (int mf = 0; mf < 4; mf++) {
            const int rl = m0 + mf * 16 + gl + rr * 8;
            const int ci = clsI[rl];
            float aRow = 0.0f, bRow = 0.0f;
            #pragma unroll
            for (int q = 0; q < 8; q++) {
                const float s = acc[mf][q >> 1][rr * 2 + (q & 1)];
                const bool same = (ci == cjr[q]);
                const float v = ex2(s * (same ? -EX2SC : EX2SC));
                const float va = same ? 0.0f : v;
                const float vb = v - va;
                aRow += va; bRow += vb;
                aCol[q] += va; bCol[q] += vb;
            }
            aRow += __shfl_xor_sync(0xffffffffu, aRow, 1);
            aRow += __shfl_xor_sync(0xffffffffu, aRow, 2);
            bRow += __shfl_xor_sync(0xffffffffu, bRow, 1);
            bRow += __shfl_xor_sync(0xffffffffu, bRow, 2);
            if (quad == 0) {
                atomicAdd(&sAccI[rl], aRow);
                atomicAdd(&sBccI[rl], bRow);
            }
        }
    }

    if (offdiag) {
        #pragma unroll
        for (int q = 0; q < 8; q++) {
            float a = aCol[q], b = bCol[q];
            #pragma unroll
            for (int o = 4; o <= 16; o <<= 1) {
                a += __shfl_xor_sync(0xffffffffu, a, o);
                b += __shfl_xor_sync(0xffffffffu, b, o);
            }
            if (lane < 4) {
                const int cl = n0 + (q >> 1) * 8 + quad * 2 + (q & 1);
                atomicAdd(&sAccJ[cl], a);
                atomicAdd(&sBccJ[cl], b);
            }
        }
    }

    __syncthreads();
    if (tid < 128) {
        atomicAdd(&g_A[iBase + tid], sAccI[tid]);
        atomicAdd(&g_B[iBase + tid], sBccI[tid]);
        if (offdiag) {
            atomicAdd(&g_A[jBase + tid], sAccJ[tid]);
            atomicAdd(&g_B[jBase + tid], sBccJ[tid]);
        }
    }
}

// ---------------------------------------------------------------------------
// k_loss: histogram locally, subtract self term, exact empty-set semantics
// ---------------------------------------------------------------------------
__global__ void k_loss(float* __restrict__ out) {
    __shared__ float red[256];
    __shared__ int hist[16];
    const int tid = threadIdx.x;
    if (tid < 16) hist[tid] = 0;
    __syncthreads();
    for (int r = tid; r < N; r += 256) atomicAdd(&hist[g_cls[r] & 15], 1);
    __syncthreads();

    const float MF = __expf(0.5f * INV_T);
    float sum = 0.0f;
    for (int r = tid; r < N; r += 256) {
        int   c   = g_cls[r] & 15;
        int   cnt = hist[c];
        float Bv  = g_B[r] - __expf(-g_selfsim[r] * INV_T);  // remove self term
        float Av  = (N - cnt > 0) ? g_A[r] : 1.0f;
        Bv        = (cnt - 1 > 0) ? Bv : 1.0f;
        sum += log1pf(MF * Av * Bv);
    }
    red[tid] = sum;
    __syncthreads();
    #pragma unroll
    for (int s = 128; s; s >>= 1) {
        if (tid < s) red[tid] += red[tid + s];
        __syncthreads();
    }
    if (tid == 0) out[0] = red[0] / (float)N;
}

// ---------------------------------------------------------------------------
extern "C" void kernel_launch(void* const* d_in, const int* in_sizes, int n_in,
                              void* d_out, int out_size) {
    const float* P = (const float*)d_in[0];
    const void*  y = d_in[1];
    float*     out = (float*)d_out;

    cudaFuncSetAttribute(k_main, cudaFuncAttributeMaxDynamicSharedMemorySize,
                         SMEM_BYTES);

    k_norm<<<N / 8, 256>>>(P, y);
    k_main<<<NTILES, 256, SMEM_BYTES>>>();
    k_loss<<<1, 256>>>(out);
}